// round 9
// baseline (speedup 1.0000x reference)
#include <cuda_runtime.h>
#include <cuda_fp16.h>
#include <cstdint>

#define BB 16
#define HH 128
#define WW 128
#define CC 256
#define KK 32
#define NPIX (HH*WW)
#define NCLS 21
#define BN_EPS 1e-3f

// ---------- encode config ----------
#define TILE_P 64
#define TPB_ENC 512
#define GRID_ENC 148
#define TILES_TOTAL (BB*(NPIX/TILE_P))   // 4096

// pitches (bytes)
#define PST   1040    // staging fp32 row pitch (1024 + 16)
#define PX2   528     // fp16 x row pitch
#define PCW2  528
#define PWT2  144     // wT row pitch

// smem layout (bytes)
#define STG   0                      // 64*1040 = 66560 fp32 staging
#define XH0   66560                  // xhi(par) = XH0 + par*33792
#define CWO   134144                 // 32*528 = 16896
#define WT0   151040                 // whi(par)=WT0+par*9216, wlo=+4608
#define X2O   169472                 // x2(par) = X2O + par*256
#define SMEM_ENC 169984

// ---------------- scratch ----------------
__device__ float g_agg[BB*KK*CC];
__device__ float g_wsum[BB*KK];
__device__ float g_attn[BB*CC];
__device__ float g_c2[KK];

// ---------------- helpers ----------------
__device__ __forceinline__ uint32_t smem_u32(const void* p){
    uint32_t a;
    asm("{ .reg .u64 t; cvta.to.shared.u64 t, %1; cvt.u32.u64 %0, t; }" : "=r"(a) : "l"(p));
    return a;
}
__device__ __forceinline__ void ldsm4(uint32_t* r, uint32_t addr){
    asm volatile("ldmatrix.sync.aligned.m8n8.x4.shared.b16 {%0,%1,%2,%3}, [%4];"
        : "=r"(r[0]),"=r"(r[1]),"=r"(r[2]),"=r"(r[3]) : "r"(addr));
}
__device__ __forceinline__ void ldsm4t(uint32_t* r, uint32_t addr){
    asm volatile("ldmatrix.sync.aligned.m8n8.x4.trans.shared.b16 {%0,%1,%2,%3}, [%4];"
        : "=r"(r[0]),"=r"(r[1]),"=r"(r[2]),"=r"(r[3]) : "r"(addr));
}
__device__ __forceinline__ void mmah(float* d,
    const uint32_t* a, uint32_t b0, uint32_t b1){
    asm volatile("mma.sync.aligned.m16n8k16.row.col.f32.f16.f16.f32 "
        "{%0,%1,%2,%3}, {%4,%5,%6,%7}, {%8,%9}, {%0,%1,%2,%3};"
        : "+f"(d[0]),"+f"(d[1]),"+f"(d[2]),"+f"(d[3])
        : "r"(a[0]),"r"(a[1]),"r"(a[2]),"r"(a[3]),"r"(b0),"r"(b1));
}
__device__ __forceinline__ uint32_t pack_h2(float a, float b){
    __half2 h = __floats2half2_rn(a, b);
    return *(uint32_t*)&h;
}
__device__ __forceinline__ uint2 hi2h(float4 v){
    return make_uint2(pack_h2(v.x, v.y), pack_h2(v.z, v.w));
}

// issue 128B of cp.async for this thread's (pA,qA) slot of `tile`
__device__ __forceinline__ void issue_cp(uint32_t sb, const float* __restrict__ x,
                                         int tile, int pA, int qA){
    const float* src = x + ((size_t)(tile*TILE_P + pA))*CC + qA*32;
    uint32_t dst = sb + STG + (uint32_t)(pA*PST + qA*128);
    #pragma unroll
    for (int i = 0; i < 8; i++)
        asm volatile("cp.async.cg.shared.global [%0], [%1], 16;"
            :: "r"(dst + i*16), "l"(src + i*4) : "memory");
    asm volatile("cp.async.commit_group;" ::: "memory");
}

// convert this thread's slot from staging -> xhi[par], x2[par]
__device__ __forceinline__ void convert_tile(char* smem, int par, int pA, int qA){
    const float4* st = (const float4*)(smem + STG + pA*PST + qA*128);
    char* xh = smem + XH0 + par*33792 + pA*PX2 + qA*64;
    float x2v = 0.f;
    #pragma unroll
    for (int i2 = 0; i2 < 4; i2++){
        float4 va = st[i2*2], vb = st[i2*2+1];
        x2v += va.x*va.x + va.y*va.y + va.z*va.z + va.w*va.w;
        x2v += vb.x*vb.x + vb.y*vb.y + vb.z*vb.z + vb.w*vb.w;
        uint2 ha = hi2h(va), hb = hi2h(vb);
        ((uint4*)xh)[i2] = make_uint4(ha.x, ha.y, hb.x, hb.y);
    }
    x2v += __shfl_xor_sync(0xffffffffu, x2v, 1);
    x2v += __shfl_xor_sync(0xffffffffu, x2v, 2);
    x2v += __shfl_xor_sync(0xffffffffu, x2v, 4);
    if (qA == 0) ((float*)(smem + X2O + par*256))[pA] = x2v;
}

// ---------------- init ----------------
__global__ void k_init(const float* __restrict__ cw){
    int t = blockIdx.x*blockDim.x + threadIdx.x;
    if (t < BB*KK*CC) g_agg[t] = 0.f;
    int t2 = t - BB*KK*CC;
    if (t2 >= 0 && t2 < BB*KK) g_wsum[t2] = 0.f;
    if (t < KK){
        float s = 0.f;
        #pragma unroll 8
        for (int c = 0; c < CC; c++){ float v = cw[t*CC + c]; s += v*v; }
        g_c2[t] = s;
    }
}

// ---------------- fused encode ----------------
__global__ __launch_bounds__(TPB_ENC, 1) void k_encode(
    const float* __restrict__ x,
    const float* __restrict__ cw,
    const float* __restrict__ smo)
{
    extern __shared__ char smem[];
    const uint32_t sb = smem_u32(smem);
    const int t = threadIdx.x;
    const int lane = t & 31;
    const int wid  = t >> 5;
    const int g4 = lane >> 2, t4 = lane & 3;

    // ---- cw -> fp16 hi plane (once) ----
    {
        const int row = t >> 4, seg = t & 15;
        const float4* crow = (const float4*)(cw + row*CC) + seg*4;
        float4 v0 = crow[0], v1 = crow[1], v2 = crow[2], v3 = crow[3];
        uint2 h0 = hi2h(v0), h1 = hi2h(v1), h2 = hi2h(v2), h3 = hi2h(v3);
        char* hdst = smem + CWO + row*PCW2 + seg*32;
        ((uint4*)hdst)[0] = make_uint4(h0.x,h0.y,h1.x,h1.y);
        ((uint4*)hdst)[1] = make_uint4(h2.x,h2.y,h3.x,h3.y);
    }

    // B-warp softmax constants
    float c2r[8], smr[8];
    if (wid < 4){
        #pragma unroll
        for (int j = 0; j < 8; j++){
            int k = (j >> 1)*8 + t4*2 + (j & 1);
            c2r[j] = g_c2[k]; smr[j] = smo[k];
        }
    }

    // accumulators
    float accC[16][4];
    #pragma unroll
    for (int i = 0; i < 16; i++)
        #pragma unroll
        for (int j = 0; j < 4; j++) accC[i][j] = 0.f;
    float wsum_acc[8];
    #pragma unroll
    for (int j = 0; j < 8; j++) wsum_acc[j] = 0.f;

    // tile range
    const int t0 = (int)(((long long)blockIdx.x     * TILES_TOTAL) / GRID_ENC);
    const int t1 = (int)(((long long)(blockIdx.x+1) * TILES_TOTAL) / GRID_ENC);

    // mappings
    const int pA = t >> 3, qA = t & 7;
    // GEMM1 (warps 0-3)
    const uint32_t aoff1 = (uint32_t)(wid*16 + (lane & 15)) * PX2 + (uint32_t)((lane >> 4) * 16);
    const uint32_t boff1 = (uint32_t)((lane & 7) + ((lane >> 4) << 3)) * PCW2
                         + (uint32_t)(((lane >> 3) & 1) * 16);
    // GEMM2 (warps 4-11): term s2 in {whi, wlo}, quadrant (m2, nh)
    const int wc = wid - 4;
    const int s2 = wc >> 2, sub = wc & 3;
    const int m2 = sub & 1, nh = sub >> 1;
    const uint32_t a2off = (uint32_t)(m2*16 + (lane & 15)) * PWT2 + (uint32_t)((lane >> 4) * 16);
    const uint32_t b2off = (uint32_t)(lane & 15) * PX2 + (uint32_t)((lane >> 4) * 16);

    // ---- prologue: cp.async tile t0, convert ----
    issue_cp(sb, x, t0, pA, qA);
    asm volatile("cp.async.wait_group 0;" ::: "memory");
    convert_tile(smem, t0 & 1, pA, qA);
    __syncthreads();

    for (int tt = t0; tt < t1; tt++){
        const int cur = tt & 1, nxt = cur ^ 1;
        const uint32_t xhiC = XH0 + (uint32_t)cur*33792;
        const uint32_t xhiN = XH0 + (uint32_t)nxt*33792;
        const bool haveNext = (tt + 1 < t1);
        const bool boundary = (tt > t0) && ((tt >> 8) != ((tt - 1) >> 8));
        const int bp = (tt - 1) >> 8;

        // prefetch next tile into staging (consumed in stage 2)
        if (haveNext) issue_cp(sb, x, tt + 1, pA, qA);

        // B-warps: wsum flush at top (covers tiles <= tt-1)
        if (wid < 4 && boundary){
            float red[8];
            #pragma unroll
            for (int j = 0; j < 8; j++){
                float s = wsum_acc[j];
                s += __shfl_xor_sync(0xffffffffu, s, 4);
                s += __shfl_xor_sync(0xffffffffu, s, 8);
                s += __shfl_xor_sync(0xffffffffu, s, 16);
                red[j] = s; wsum_acc[j] = 0.f;
            }
            if (g4 == 0){
                #pragma unroll
                for (int j = 0; j < 8; j++){
                    int k = (j >> 1)*8 + t4*2 + (j & 1);
                    atomicAdd(&g_wsum[bp*KK + k], red[j]);
                }
            }
        }

        // ---- stage 1 ----
        if (wid < 4){
            // GEMM1: D1[p 16][k 32] = xhi . cwhi^T
            float d[4][4];
            #pragma unroll
            for (int i = 0; i < 4; i++)
                #pragma unroll
                for (int j = 0; j < 4; j++) d[i][j] = 0.f;
            #pragma unroll 4
            for (int kt = 0; kt < 16; kt++){
                uint32_t a[4], b0[4], b1[4];
                ldsm4(a,  sb + xhiC + aoff1 + kt*32);
                ldsm4(b0, sb + CWO + boff1 + kt*32);
                ldsm4(b1, sb + CWO + boff1 + 16*PCW2 + kt*32);
                mmah(d[0], a, b0[0], b0[1]);
                mmah(d[1], a, b0[2], b0[3]);
                mmah(d[2], a, b1[0], b1[1]);
                mmah(d[3], a, b1[2], b1[3]);
            }
            // softmax from fragments
            const int px0 = wid*16 + g4, px1 = px0 + 8;
            const float* x2p = (const float*)(smem + X2O + cur*256);
            const float xa = x2p[px0], xb = x2p[px1];
            float ea[8], eb[8];
            float mxa = -1e30f, mxb = -1e30f;
            #pragma unroll
            for (int j = 0; j < 8; j++){
                int nt = j >> 1, i = j & 1;
                float la = (xa - 2.f*d[nt][i]     + c2r[j]) * smr[j];
                float lb = (xb - 2.f*d[nt][2 + i] + c2r[j]) * smr[j];
                ea[j] = la; eb[j] = lb;
                mxa = fmaxf(mxa, la); mxb = fmaxf(mxb, lb);
            }
            mxa = fmaxf(mxa, __shfl_xor_sync(0xffffffffu, mxa, 1));
            mxa = fmaxf(mxa, __shfl_xor_sync(0xffffffffu, mxa, 2));
            mxb = fmaxf(mxb, __shfl_xor_sync(0xffffffffu, mxb, 1));
            mxb = fmaxf(mxb, __shfl_xor_sync(0xffffffffu, mxb, 2));
            float sa = 0.f, sbv = 0.f;
            #pragma unroll
            for (int j = 0; j < 8; j++){
                ea[j] = __expf(ea[j] - mxa); sa  += ea[j];
                eb[j] = __expf(eb[j] - mxb); sbv += eb[j];
            }
            sa  += __shfl_xor_sync(0xffffffffu, sa, 1);
            sa  += __shfl_xor_sync(0xffffffffu, sa, 2);
            sbv += __shfl_xor_sync(0xffffffffu, sbv, 1);
            sbv += __shfl_xor_sync(0xffffffffu, sbv, 2);
            const float inva = 1.f / sa, invb = 1.f / sbv;
            char* wh = smem + WT0 + cur*9216;
            char* wl = wh + 4608;
            #pragma unroll
            for (int j = 0; j < 8; j++){
                int k = (j >> 1)*8 + t4*2 + (j & 1);
                float wa = ea[j]*inva, wb = eb[j]*invb;
                wsum_acc[j] += wa + wb;
                __half ha = __float2half_rn(wa);
                __half hb = __float2half_rn(wb);
                *(__half*)(wh + k*PWT2 + px0*2) = ha;
                *(__half*)(wh + k*PWT2 + px1*2) = hb;
                *(__half*)(wl + k*PWT2 + px0*2) = __float2half_rn(wa - __half2float(ha));
                *(__half*)(wl + k*PWT2 + px1*2) = __float2half_rn(wb - __half2float(hb));
            }
        } else if (wid < 12 && tt > t0){
            // GEMM2(tt-1): term s2 in {whi.xhi, wlo.xhi}
            const uint32_t apl = WT0 + (uint32_t)nxt*9216 + (s2 ? 4608u : 0u);
            #pragma unroll
            for (int pt = 0; pt < 4; pt++){
                uint32_t af[4];
                ldsm4(af, sb + apl + a2off + pt*32);
                #pragma unroll
                for (int hf = 0; hf < 8; hf++){
                    uint32_t bf[4];
                    ldsm4t(bf, sb + xhiN + b2off + pt*16*PX2 + (uint32_t)(nh*128 + hf*16)*2);
                    mmah(accC[hf*2    ], af, bf[0], bf[1]);
                    mmah(accC[hf*2 + 1], af, bf[2], bf[3]);
                }
            }
        }
        __syncthreads();

        // C-warps: accC flush (covers tiles <= tt-1)
        if (wid >= 4 && wid < 12 && boundary){
            const int k1 = m2*16 + g4;
            #pragma unroll
            for (int nt = 0; nt < 16; nt++){
                float* base = g_agg + ((size_t)bp*KK + k1)*CC + nh*128 + nt*8 + t4*2;
                atomicAdd(base,            accC[nt][0]);
                atomicAdd(base + 1,        accC[nt][1]);
                atomicAdd(base + 8*CC,     accC[nt][2]);
                atomicAdd(base + 8*CC + 1, accC[nt][3]);
                accC[nt][0] = accC[nt][1] = accC[nt][2] = accC[nt][3] = 0.f;
            }
        }

        // ---- stage 2: wait cp.async, convert tile tt+1 into buf nxt ----
        if (haveNext){
            asm volatile("cp.async.wait_group 0;" ::: "memory");
            convert_tile(smem, nxt, pA, qA);
        }
        __syncthreads();
    }

    // ---- epilogue ----
    const int bl2 = (t1 - 1) >> 8;
    if (wid >= 4 && wid < 12){
        const int lp = (t1 - 1) & 1;
        const uint32_t xhiL = XH0 + (uint32_t)lp*33792;
        const uint32_t apl = WT0 + (uint32_t)lp*9216 + (s2 ? 4608u : 0u);
        #pragma unroll
        for (int pt = 0; pt < 4; pt++){
            uint32_t af[4];
            ldsm4(af, sb + apl + a2off + pt*32);
            #pragma unroll
            for (int hf = 0; hf < 8; hf++){
                uint32_t bf[4];
                ldsm4t(bf, sb + xhiL + b2off + pt*16*PX2 + (uint32_t)(nh*128 + hf*16)*2);
                mmah(accC[hf*2    ], af, bf[0], bf[1]);
                mmah(accC[hf*2 + 1], af, bf[2], bf[3]);
            }
        }
        const int k1 = m2*16 + g4;
        #pragma unroll
        for (int nt = 0; nt < 16; nt++){
            float* base = g_agg + ((size_t)bl2*KK + k1)*CC + nh*128 + nt*8 + t4*2;
            atomicAdd(base,            accC[nt][0]);
            atomicAdd(base + 1,        accC[nt][1]);
            atomicAdd(base + 8*CC,     accC[nt][2]);
            atomicAdd(base + 8*CC + 1, accC[nt][3]);
        }
    } else if (wid < 4){
        float red[8];
        #pragma unroll
        for (int j = 0; j < 8; j++){
            float s = wsum_acc[j];
            s += __shfl_xor_sync(0xffffffffu, s, 4);
            s += __shfl_xor_sync(0xffffffffu, s, 8);
            s += __shfl_xor_sync(0xffffffffu, s, 16);
            red[j] = s;
        }
        if (g4 == 0){
            #pragma unroll
            for (int j = 0; j < 8; j++){
                int k = (j >> 1)*8 + t4*2 + (j & 1);
                atomicAdd(&g_wsum[bl2*KK + k], red[j]);
            }
        }
    }
}

// ---------------- heads ----------------
__global__ void k_heads(
    const float* __restrict__ cw,
    const float* __restrict__ gamma, const float* __restrict__ beta,
    const float* __restrict__ mean,  const float* __restrict__ var,
    const float* __restrict__ Wenc,  const float* __restrict__ benc,
    const float* __restrict__ Wse,   const float* __restrict__ bse,
    float* __restrict__ out)
{
    const int b = blockIdx.x;
    const int c = threadIdx.x;
    __shared__ float enc[CC];

    float acc = 0.f;
    #pragma unroll
    for (int k = 0; k < KK; k++){
        float a  = g_agg[(b*KK + k)*CC + c] - g_wsum[b*KK + k] * cw[k*CC + c];
        float bn = (a - mean[k]) * rsqrtf(var[k] + BN_EPS) * gamma[k] + beta[k];
        acc += fmaxf(bn, 0.f);
    }
    enc[c] = acc;
    __syncthreads();

    float s = benc[c];
    #pragma unroll 8
    for (int i = 0; i < CC; i++) s += enc[i] * Wenc[i*CC + c];
    g_attn[b*CC + c] = 1.f / (1.f + __expf(-s));

    if (c < NCLS){
        float s2 = bse[c];
        #pragma unroll 8
        for (int i = 0; i < CC; i++) s2 += enc[i] * Wse[i*NCLS + c];
        out[(size_t)BB*NPIX*CC + b*NCLS + c] = 1.f / (1.f + __expf(-s2));
    }
}

// ---------------- rescale ----------------
__global__ void k_scale(const float* __restrict__ x, float* __restrict__ out){
    const int F4 = NPIX*CC/4;
    int idx = blockIdx.x*blockDim.x + threadIdx.x;
    int b  = idx / F4;
    int r  = idx - b*F4;
    int c4 = r & 63;
    float4 a = ((const float4*)g_attn)[b*64 + c4];
    float4 v = __ldcs((const float4*)x + idx);
    v.x *= a.x; v.y *= a.y; v.z *= a.z; v.w *= a.w;
    __stcs((float4*)out + idx, v);
}

extern "C" void kernel_launch(void* const* d_in, const int* in_sizes, int n_in,
                              void* d_out, int out_size)
{
    const float* x     = (const float*)d_in[0];
    const float* cw    = (const float*)d_in[1];
    const float* smo   = (const float*)d_in[2];
    const float* gamma = (const float*)d_in[3];
    const float* beta  = (const float*)d_in[4];
    const float* mean  = (const float*)d_in[5];
    const float* var   = (const float*)d_in[6];
    const float* Wenc  = (const float*)d_in[7];
    const float* benc  = (const float*)d_in[8];
    const float* Wse   = (const float*)d_in[9];
    const float* bse   = (const float*)d_in[10];
    float* out = (float*)d_out;

    cudaFuncSetAttribute(k_encode, cudaFuncAttributeMaxDynamicSharedMemorySize, SMEM_ENC);

    int init_total = BB*KK*CC + BB*KK;
    k_init<<<(init_total + 255)/256, 256>>>(cw);
    k_encode<<<GRID_ENC, TPB_ENC, SMEM_ENC>>>(x, cw, smo);
    k_heads<<<BB, CC>>>(cw, gamma, beta, mean, var, Wenc, benc, Wse, bse, out);
    k_scale<<<(BB*NPIX*CC/4)/256, 256>>>(x, out);
}

// round 10
// speedup vs baseline: 1.1587x; 1.1587x over previous
#include <cuda_runtime.h>
#include <cuda_fp16.h>
#include <cstdint>

#define BB 16
#define HH 128
#define WW 128
#define CC 256
#define KK 32
#define NPIX (HH*WW)
#define NCLS 21
#define BN_EPS 1e-3f

// ---------- encode config ----------
#define TILE_P 64
#define TPB_ENC 512
#define GRID_ENC 148
#define TILES_TOTAL (BB*(NPIX/TILE_P))   // 4096

// pitches (bytes)
#define PX2   528     // fp16 x row pitch
#define PCW2  528
#define PWT2  144

// smem layout (bytes)
#define STG   0                      // 64*1024 = 65536, swizzled fp32 staging
#define XH0   65536                  // xhi(par) = XH0 + par*67584 ; xlo = +33792
#define XPAR  67584
#define CWO   200704                 // 16896
#define WT0   217600                 // whi 4608 + wlo 4608
#define X2O   226816                 // x2(par) = X2O + par*256
#define SMEM_ENC 227328

// ---------------- scratch ----------------
__device__ float g_agg[BB*KK*CC];
__device__ float g_wsum[BB*KK];
__device__ float g_attn[BB*CC];
__device__ float g_c2[KK];

// ---------------- helpers ----------------
__device__ __forceinline__ uint32_t smem_u32(const void* p){
    uint32_t a;
    asm("{ .reg .u64 t; cvta.to.shared.u64 t, %1; cvt.u32.u64 %0, t; }" : "=r"(a) : "l"(p));
    return a;
}
__device__ __forceinline__ uint32_t swzs(uint32_t o){ return o ^ ((o >> 3) & 0x70u); }
__device__ __forceinline__ void ldsm4(uint32_t* r, uint32_t addr){
    asm volatile("ldmatrix.sync.aligned.m8n8.x4.shared.b16 {%0,%1,%2,%3}, [%4];"
        : "=r"(r[0]),"=r"(r[1]),"=r"(r[2]),"=r"(r[3]) : "r"(addr));
}
__device__ __forceinline__ void ldsm4t(uint32_t* r, uint32_t addr){
    asm volatile("ldmatrix.sync.aligned.m8n8.x4.trans.shared.b16 {%0,%1,%2,%3}, [%4];"
        : "=r"(r[0]),"=r"(r[1]),"=r"(r[2]),"=r"(r[3]) : "r"(addr));
}
__device__ __forceinline__ void mmah(float* d,
    const uint32_t* a, uint32_t b0, uint32_t b1){
    asm volatile("mma.sync.aligned.m16n8k16.row.col.f32.f16.f16.f32 "
        "{%0,%1,%2,%3}, {%4,%5,%6,%7}, {%8,%9}, {%0,%1,%2,%3};"
        : "+f"(d[0]),"+f"(d[1]),"+f"(d[2]),"+f"(d[3])
        : "r"(a[0]),"r"(a[1]),"r"(a[2]),"r"(a[3]),"r"(b0),"r"(b1));
}
__device__ __forceinline__ uint32_t pack_h2(float a, float b){
    __half2 h = __floats2half2_rn(a, b);
    return *(uint32_t*)&h;
}
__device__ __forceinline__ uint2 hi2h(float4 v){
    return make_uint2(pack_h2(v.x, v.y), pack_h2(v.z, v.w));
}
__device__ __forceinline__ float4 residual_h(float4 v, uint2 h){
    __half2 a = *(__half2*)&h.x;
    __half2 b = *(__half2*)&h.y;
    return make_float4(v.x - __half2float(a.x), v.y - __half2float(a.y),
                       v.z - __half2float(b.x), v.w - __half2float(b.y));
}

// cp.async one 128B slot of `tile` into swizzled staging. slot s in [0,512)
__device__ __forceinline__ void issue_cp_slot(uint32_t sb, const float* __restrict__ x,
                                              int tile, int s){
    const int row = s >> 3, q = s & 7;
    const float* src = x + ((size_t)(tile*TILE_P + row))*CC + q*32;
    const uint32_t dstrow = sb + STG + (uint32_t)row*1024u;
    #pragma unroll
    for (int i = 0; i < 8; i++)
        asm volatile("cp.async.cg.shared.global [%0], [%1], 16;"
            :: "r"(dstrow + swzs((uint32_t)(q*128 + i*16))), "l"(src + i*4) : "memory");
}

// convert slot s (row pA, chunk j): staging -> xhi/xlo[par], x2 partial via 8-lane shuffle
__device__ __forceinline__ void convert_slot(char* smem, int par, int s){
    const int pA = s >> 3, j = s & 7;
    const char* strow = smem + STG + pA*1024;
    char* xh = smem + XH0 + par*XPAR + pA*PX2 + j*16;
    char* xl = xh + 33792;
    float x2v = 0.f;
    #pragma unroll
    for (int i2 = 0; i2 < 4; i2++){
        const uint32_t o = (uint32_t)(32*j + 256*i2);
        float4 va = *(const float4*)(strow + swzs(o));
        float4 vb = *(const float4*)(strow + swzs(o + 16));
        x2v += va.x*va.x + va.y*va.y + va.z*va.z + va.w*va.w;
        x2v += vb.x*vb.x + vb.y*vb.y + vb.z*vb.z + vb.w*vb.w;
        uint2 ha = hi2h(va), hb = hi2h(vb);
        uint2 la = hi2h(residual_h(va, ha)), lb = hi2h(residual_h(vb, hb));
        *(uint4*)(xh + i2*128) = make_uint4(ha.x, ha.y, hb.x, hb.y);
        *(uint4*)(xl + i2*128) = make_uint4(la.x, la.y, lb.x, lb.y);
    }
    x2v += __shfl_xor_sync(0xffffffffu, x2v, 1);
    x2v += __shfl_xor_sync(0xffffffffu, x2v, 2);
    x2v += __shfl_xor_sync(0xffffffffu, x2v, 4);
    if (j == 0) ((float*)(smem + X2O + par*256))[pA] = x2v;
}

// ---------------- init ----------------
__global__ void k_init(const float* __restrict__ cw){
    int t = blockIdx.x*blockDim.x + threadIdx.x;
    if (t < BB*KK*CC) g_agg[t] = 0.f;
    int t2 = t - BB*KK*CC;
    if (t2 >= 0 && t2 < BB*KK) g_wsum[t2] = 0.f;
    if (t < KK){
        float s = 0.f;
        #pragma unroll 8
        for (int c = 0; c < CC; c++){ float v = cw[t*CC + c]; s += v*v; }
        g_c2[t] = s;
    }
}

// ---------------- fused encode ----------------
__global__ __launch_bounds__(TPB_ENC, 1) void k_encode(
    const float* __restrict__ x,
    const float* __restrict__ cw,
    const float* __restrict__ smo)
{
    extern __shared__ char smem[];
    const uint32_t sb = smem_u32(smem);
    const int t = threadIdx.x;
    const int lane = t & 31;
    const int wid  = t >> 5;
    const int g4 = lane >> 2, t4 = lane & 3;

    // ---- cw -> fp16 hi plane (once) ----
    {
        const int row = t >> 4, seg = t & 15;
        const float4* crow = (const float4*)(cw + row*CC) + seg*4;
        float4 v0 = crow[0], v1 = crow[1], v2 = crow[2], v3 = crow[3];
        uint2 h0 = hi2h(v0), h1 = hi2h(v1), h2 = hi2h(v2), h3 = hi2h(v3);
        char* hdst = smem + CWO + row*PCW2 + seg*32;
        ((uint4*)hdst)[0] = make_uint4(h0.x,h0.y,h1.x,h1.y);
        ((uint4*)hdst)[1] = make_uint4(h2.x,h2.y,h3.x,h3.y);
    }

    // B-warp softmax constants
    float c2r[8], smr[8];
    if (wid < 4){
        #pragma unroll
        for (int j = 0; j < 8; j++){
            int k = (j >> 1)*8 + t4*2 + (j & 1);
            c2r[j] = g_c2[k]; smr[j] = smo[k];
        }
    }

    // accumulators (converter/GEMM2 warps use accC; B-warps use wsum)
    float accC[16][4];
    #pragma unroll
    for (int i = 0; i < 16; i++)
        #pragma unroll
        for (int j = 0; j < 4; j++) accC[i][j] = 0.f;
    float wsum_acc[8];
    #pragma unroll
    for (int j = 0; j < 8; j++) wsum_acc[j] = 0.f;

    // tile range
    const int t0 = (int)(((long long)blockIdx.x     * TILES_TOTAL) / GRID_ENC);
    const int t1 = (int)(((long long)(blockIdx.x+1) * TILES_TOTAL) / GRID_ENC);

    // GEMM1 (warps 0-3)
    const uint32_t aoff1 = (uint32_t)(wid*16 + (lane & 15)) * PX2 + (uint32_t)((lane >> 4) * 16);
    const uint32_t boff1 = (uint32_t)((lane & 7) + ((lane >> 4) << 3)) * PCW2
                         + (uint32_t)(((lane >> 3) & 1) * 16);
    // GEMM2 (warps 4-15): term s2 in {whi.xhi, whi.xlo, wlo.xhi}, quadrant (m2, nh)
    const int wc = wid - 4;
    const int s2 = wc >> 2, sub = wc & 3;
    const int m2 = sub & 1, nh = sub >> 1;
    const uint32_t a2off = (uint32_t)(m2*16 + (lane & 15)) * PWT2 + (uint32_t)((lane >> 4) * 16);
    const uint32_t b2off = (uint32_t)(lane & 15) * PX2 + (uint32_t)((lane >> 4) * 16);

    // ---- prologue: stage + convert tile t0 ----
    issue_cp_slot(sb, x, t0, t);
    asm volatile("cp.async.commit_group;" ::: "memory");
    asm volatile("cp.async.wait_group 0;" ::: "memory");
    __syncthreads();
    convert_slot(smem, t0 & 1, t);
    __syncthreads();

    for (int tt = t0; tt < t1; tt++){
        const int cur = tt & 1, nxt = cur ^ 1;
        const uint32_t xhiC = XH0 + (uint32_t)cur*XPAR;
        const uint32_t xloC = xhiC + 33792;
        const bool haveNext = (tt + 1 < t1);
        const bool boundary = (tt > t0) && ((tt >> 8) != ((tt - 1) >> 8));
        const int bp = (tt - 1) >> 8;

        // prefetch next tile (converter warps only; slots t-128 and t+256)
        if (wid >= 4 && haveNext){
            issue_cp_slot(sb, x, tt + 1, t - 128);
            if (t < 256) issue_cp_slot(sb, x, tt + 1, t + 256);
            asm volatile("cp.async.commit_group;" ::: "memory");
        }

        // batch-boundary flushes (registers + global atomics only)
        if (boundary){
            if (wid < 4){
                float red[8];
                #pragma unroll
                for (int j = 0; j < 8; j++){
                    float s = wsum_acc[j];
                    s += __shfl_xor_sync(0xffffffffu, s, 4);
                    s += __shfl_xor_sync(0xffffffffu, s, 8);
                    s += __shfl_xor_sync(0xffffffffu, s, 16);
                    red[j] = s; wsum_acc[j] = 0.f;
                }
                if (g4 == 0){
                    #pragma unroll
                    for (int j = 0; j < 8; j++){
                        int k = (j >> 1)*8 + t4*2 + (j & 1);
                        atomicAdd(&g_wsum[bp*KK + k], red[j]);
                    }
                }
            } else {
                const int k1 = m2*16 + g4;
                #pragma unroll
                for (int nt = 0; nt < 16; nt++){
                    float* base = g_agg + ((size_t)bp*KK + k1)*CC + nh*128 + nt*8 + t4*2;
                    atomicAdd(base,            accC[nt][0]);
                    atomicAdd(base + 1,        accC[nt][1]);
                    atomicAdd(base + 8*CC,     accC[nt][2]);
                    atomicAdd(base + 8*CC + 1, accC[nt][3]);
                    accC[nt][0] = accC[nt][1] = accC[nt][2] = accC[nt][3] = 0.f;
                }
            }
        }

        // ---- stage 1: GEMM1+softmax+wT (warps 0-3) | convert tile tt+1 (warps 4-15) ----
        if (wid < 4){
            float d[4][4];
            #pragma unroll
            for (int i = 0; i < 4; i++)
                #pragma unroll
                for (int j = 0; j < 4; j++) d[i][j] = 0.f;
            #pragma unroll 4
            for (int kt = 0; kt < 16; kt++){
                uint32_t a[4], b0[4], b1[4];
                ldsm4(a,  sb + xhiC + aoff1 + kt*32);
                ldsm4(b0, sb + CWO + boff1 + kt*32);
                ldsm4(b1, sb + CWO + boff1 + 16*PCW2 + kt*32);
                mmah(d[0], a, b0[0], b0[1]);
                mmah(d[1], a, b0[2], b0[3]);
                mmah(d[2], a, b1[0], b1[1]);
                mmah(d[3], a, b1[2], b1[3]);
            }
            const int px0 = wid*16 + g4, px1 = px0 + 8;
            const float* x2p = (const float*)(smem + X2O + cur*256);
            const float xa = x2p[px0], xb = x2p[px1];
            float ea[8], eb[8];
            float mxa = -1e30f, mxb = -1e30f;
            #pragma unroll
            for (int j = 0; j < 8; j++){
                int nt = j >> 1, i = j & 1;
                float la = (xa - 2.f*d[nt][i]     + c2r[j]) * smr[j];
                float lb = (xb - 2.f*d[nt][2 + i] + c2r[j]) * smr[j];
                ea[j] = la; eb[j] = lb;
                mxa = fmaxf(mxa, la); mxb = fmaxf(mxb, lb);
            }
            mxa = fmaxf(mxa, __shfl_xor_sync(0xffffffffu, mxa, 1));
            mxa = fmaxf(mxa, __shfl_xor_sync(0xffffffffu, mxa, 2));
            mxb = fmaxf(mxb, __shfl_xor_sync(0xffffffffu, mxb, 1));
            mxb = fmaxf(mxb, __shfl_xor_sync(0xffffffffu, mxb, 2));
            float sa = 0.f, sbv = 0.f;
            #pragma unroll
            for (int j = 0; j < 8; j++){
                ea[j] = __expf(ea[j] - mxa); sa  += ea[j];
                eb[j] = __expf(eb[j] - mxb); sbv += eb[j];
            }
            sa  += __shfl_xor_sync(0xffffffffu, sa, 1);
            sa  += __shfl_xor_sync(0xffffffffu, sa, 2);
            sbv += __shfl_xor_sync(0xffffffffu, sbv, 1);
            sbv += __shfl_xor_sync(0xffffffffu, sbv, 2);
            const float inva = 1.f / sa, invb = 1.f / sbv;
            char* wh = smem + WT0;
            char* wl = wh + 4608;
            #pragma unroll
            for (int j = 0; j < 8; j++){
                int k = (j >> 1)*8 + t4*2 + (j & 1);
                float wa = ea[j]*inva, wb = eb[j]*invb;
                wsum_acc[j] += wa + wb;
                __half ha = __float2half_rn(wa);
                __half hb = __float2half_rn(wb);
                *(__half*)(wh + k*PWT2 + px0*2) = ha;
                *(__half*)(wh + k*PWT2 + px1*2) = hb;
                *(__half*)(wl + k*PWT2 + px0*2) = __float2half_rn(wa - __half2float(ha));
                *(__half*)(wl + k*PWT2 + px1*2) = __float2half_rn(wb - __half2float(hb));
            }
        } else if (haveNext){
            asm volatile("cp.async.wait_group 0;" ::: "memory");
            asm volatile("bar.sync 1, 384;" ::: "memory");   // staging visible across converter warps
            convert_slot(smem, nxt, t - 128);
            if (t < 256) convert_slot(smem, nxt, t + 256);
        }
        __syncthreads();

        // ---- stage 2: GEMM2(tt) on warps 4-15 ----
        if (wid >= 4){
            const uint32_t apl = WT0 + (s2 == 2 ? 4608u : 0u);
            const uint32_t bpl = (s2 == 1) ? xloC : xhiC;
            #pragma unroll
            for (int pt = 0; pt < 4; pt++){
                uint32_t af[4];
                ldsm4(af, sb + apl + a2off + pt*32);
                #pragma unroll
                for (int hf = 0; hf < 8; hf++){
                    uint32_t bf[4];
                    ldsm4t(bf, sb + bpl + b2off + pt*16*PX2 + (uint32_t)(nh*128 + hf*16)*2);
                    mmah(accC[hf*2    ], af, bf[0], bf[1]);
                    mmah(accC[hf*2 + 1], af, bf[2], bf[3]);
                }
            }
        }
        __syncthreads();
    }

    // ---- epilogue flushes ----
    const int bl2 = (t1 - 1) >> 8;
    if (wid >= 4){
        const int k1 = m2*16 + g4;
        #pragma unroll
        for (int nt = 0; nt < 16; nt++){
            float* base = g_agg + ((size_t)bl2*KK + k1)*CC + nh*128 + nt*8 + t4*2;
            atomicAdd(base,            accC[nt][0]);
            atomicAdd(base + 1,        accC[nt][1]);
            atomicAdd(base + 8*CC,     accC[nt][2]);
            atomicAdd(base + 8*CC + 1, accC[nt][3]);
        }
    } else {
        float red[8];
        #pragma unroll
        for (int j = 0; j < 8; j++){
            float s = wsum_acc[j];
            s += __shfl_xor_sync(0xffffffffu, s, 4);
            s += __shfl_xor_sync(0xffffffffu, s, 8);
            s += __shfl_xor_sync(0xffffffffu, s, 16);
            red[j] = s;
        }
        if (g4 == 0){
            #pragma unroll
            for (int j = 0; j < 8; j++){
                int k = (j >> 1)*8 + t4*2 + (j & 1);
                atomicAdd(&g_wsum[bl2*KK + k], red[j]);
            }
        }
    }
}

// ---------------- heads ----------------
__global__ void k_heads(
    const float* __restrict__ cw,
    const float* __restrict__ gamma, const float* __restrict__ beta,
    const float* __restrict__ mean,  const float* __restrict__ var,
    const float* __restrict__ Wenc,  const float* __restrict__ benc,
    const float* __restrict__ Wse,   const float* __restrict__ bse,
    float* __restrict__ out)
{
    const int b = blockIdx.x;
    const int c = threadIdx.x;
    __shared__ float enc[CC];

    float acc = 0.f;
    #pragma unroll
    for (int k = 0; k < KK; k++){
        float a  = g_agg[(b*KK + k)*CC + c] - g_wsum[b*KK + k] * cw[k*CC + c];
        float bn = (a - mean[k]) * rsqrtf(var[k] + BN_EPS) * gamma[k] + beta[k];
        acc += fmaxf(bn, 0.f);
    }
    enc[c] = acc;
    __syncthreads();

    float s = benc[c];
    #pragma unroll 8
    for (int i = 0; i < CC; i++) s += enc[i] * Wenc[i*CC + c];
    g_attn[b*CC + c] = 1.f / (1.f + __expf(-s));

    if (c < NCLS){
        float s2 = bse[c];
        #pragma unroll 8
        for (int i = 0; i < CC; i++) s2 += enc[i] * Wse[i*NCLS + c];
        out[(size_t)BB*NPIX*CC + b*NCLS + c] = 1.f / (1.f + __expf(-s2));
    }
}

// ---------------- rescale ----------------
__global__ void k_scale(const float* __restrict__ x, float* __restrict__ out){
    const int F4 = NPIX*CC/4;
    int idx = blockIdx.x*blockDim.x + threadIdx.x;
    int b  = idx / F4;
    int r  = idx - b*F4;
    int c4 = r & 63;
    float4 a = ((const float4*)g_attn)[b*64 + c4];
    float4 v = __ldcs((const float4*)x + idx);
    v.x *= a.x; v.y *= a.y; v.z *= a.z; v.w *= a.w;
    __stcs((float4*)out + idx, v);
}

extern "C" void kernel_launch(void* const* d_in, const int* in_sizes, int n_in,
                              void* d_out, int out_size)
{
    const float* x     = (const float*)d_in[0];
    const float* cw    = (const float*)d_in[1];
    const float* smo   = (const float*)d_in[2];
    const float* gamma = (const float*)d_in[3];
    const float* beta  = (const float*)d_in[4];
    const float* mean  = (const float*)d_in[5];
    const float* var   = (const float*)d_in[6];
    const float* Wenc  = (const float*)d_in[7];
    const float* benc  = (const float*)d_in[8];
    const float* Wse   = (const float*)d_in[9];
    const float* bse   = (const float*)d_in[10];
    float* out = (float*)d_out;

    cudaFuncSetAttribute(k_encode, cudaFuncAttributeMaxDynamicSharedMemorySize, SMEM_ENC);

    int init_total = BB*KK*CC + BB*KK;
    k_init<<<(init_total + 255)/256, 256>>>(cw);
    k_encode<<<GRID_ENC, TPB_ENC, SMEM_ENC>>>(x, cw, smo);
    k_heads<<<BB, CC>>>(cw, gamma, beta, mean, var, Wenc, benc, Wse, bse, out);
    k_scale<<<(BB*NPIX*CC/4)/256, 256>>>(x, out);
}

// round 11
// speedup vs baseline: 1.2638x; 1.0906x over previous
#include <cuda_runtime.h>
#include <cuda_fp16.h>
#include <cstdint>

#define BB 16
#define HH 128
#define WW 128
#define CC 256
#define KK 32
#define NPIX (HH*WW)
#define NCLS 21
#define BN_EPS 1e-3f

// ---------- encode config ----------
#define TILE_P 64
#define TPB_ENC 512
#define GRID_ENC 148
#define TILES_TOTAL (BB*(NPIX/TILE_P))   // 4096

// pitches (bytes)
#define PX2   528     // fp16 x row pitch
#define PCW2  528
#define PWT2  144

// smem layout (bytes)
#define XH0   0                      // xhi(par) = XH0 + par*XPAR ; xlo = +33792
#define XPAR  67584                  // 2 buffers -> 135168
#define CWO   135168                 // 16896
#define WT0   152064                 // buf(par) = WT0 + par*9216 (whi 4608 + wlo 4608)
#define X2O   170496                 // x2(par) = X2O + par*256
#define SMEM_ENC 171008

// ---------------- scratch ----------------
__device__ float g_agg[BB*KK*CC];
__device__ float g_wsum[BB*KK];
__device__ float g_attn[BB*CC];
__device__ float g_c2[KK];

// ---------------- helpers ----------------
__device__ __forceinline__ uint32_t smem_u32(const void* p){
    uint32_t a;
    asm("{ .reg .u64 t; cvta.to.shared.u64 t, %1; cvt.u32.u64 %0, t; }" : "=r"(a) : "l"(p));
    return a;
}
__device__ __forceinline__ void ldsm4(uint32_t* r, uint32_t addr){
    asm volatile("ldmatrix.sync.aligned.m8n8.x4.shared.b16 {%0,%1,%2,%3}, [%4];"
        : "=r"(r[0]),"=r"(r[1]),"=r"(r[2]),"=r"(r[3]) : "r"(addr));
}
__device__ __forceinline__ void ldsm4t(uint32_t* r, uint32_t addr){
    asm volatile("ldmatrix.sync.aligned.m8n8.x4.trans.shared.b16 {%0,%1,%2,%3}, [%4];"
        : "=r"(r[0]),"=r"(r[1]),"=r"(r[2]),"=r"(r[3]) : "r"(addr));
}
__device__ __forceinline__ void mmah(float* d,
    const uint32_t* a, uint32_t b0, uint32_t b1){
    asm volatile("mma.sync.aligned.m16n8k16.row.col.f32.f16.f16.f32 "
        "{%0,%1,%2,%3}, {%4,%5,%6,%7}, {%8,%9}, {%0,%1,%2,%3};"
        : "+f"(d[0]),"+f"(d[1]),"+f"(d[2]),"+f"(d[3])
        : "r"(a[0]),"r"(a[1]),"r"(a[2]),"r"(a[3]),"r"(b0),"r"(b1));
}
__device__ __forceinline__ uint32_t pack_h2(float a, float b){
    __half2 h = __floats2half2_rn(a, b);
    return *(uint32_t*)&h;
}
__device__ __forceinline__ uint2 hi2h(float4 v){
    return make_uint2(pack_h2(v.x, v.y), pack_h2(v.z, v.w));
}
__device__ __forceinline__ float4 residual_h(float4 v, uint2 h){
    __half2 a = *(__half2*)&h.x;
    __half2 b = *(__half2*)&h.y;
    return make_float4(v.x - __half2float(a.x), v.y - __half2float(a.y),
                       v.z - __half2float(b.x), v.w - __half2float(b.y));
}

// LDG one slot (32 floats, 4 strided groups of 8) of `tile` into v[8]
__device__ __forceinline__ void ldg_slot(float4* v, const float* __restrict__ x,
                                         int tile, int s){
    const int pA = s >> 3, j = s & 7;
    const float* src = x + ((size_t)(tile*TILE_P + pA))*CC + j*8;
    #pragma unroll
    for (int i2 = 0; i2 < 4; i2++){
        v[2*i2]   = *(const float4*)(src + i2*64);
        v[2*i2+1] = *(const float4*)(src + i2*64 + 4);
    }
}

// convert v[8] of slot s into x planes[par] (conflict-free layout) + x2 partial
__device__ __forceinline__ void convert_slot(char* smem, const float4* v, int par, int s){
    const int pA = s >> 3, j = s & 7;
    char* xh = smem + XH0 + par*XPAR + pA*PX2 + j*16;
    char* xl = xh + 33792;
    float x2v = 0.f;
    #pragma unroll
    for (int i2 = 0; i2 < 4; i2++){
        float4 va = v[2*i2], vb = v[2*i2+1];
        x2v += va.x*va.x + va.y*va.y + va.z*va.z + va.w*va.w;
        x2v += vb.x*vb.x + vb.y*vb.y + vb.z*vb.z + vb.w*vb.w;
        uint2 ha = hi2h(va), hb = hi2h(vb);
        uint2 la = hi2h(residual_h(va, ha)), lb = hi2h(residual_h(vb, hb));
        *(uint4*)(xh + i2*128) = make_uint4(ha.x, ha.y, hb.x, hb.y);
        *(uint4*)(xl + i2*128) = make_uint4(la.x, la.y, lb.x, lb.y);
    }
    x2v += __shfl_xor_sync(0xffffffffu, x2v, 1);
    x2v += __shfl_xor_sync(0xffffffffu, x2v, 2);
    x2v += __shfl_xor_sync(0xffffffffu, x2v, 4);
    if (j == 0) ((float*)(smem + X2O + par*256))[pA] = x2v;
}

// ---------------- init ----------------
__global__ void k_init(const float* __restrict__ cw){
    int t = blockIdx.x*blockDim.x + threadIdx.x;
    if (t < BB*KK*CC) g_agg[t] = 0.f;
    int t2 = t - BB*KK*CC;
    if (t2 >= 0 && t2 < BB*KK) g_wsum[t2] = 0.f;
    if (t < KK){
        float s = 0.f;
        #pragma unroll 8
        for (int c = 0; c < CC; c++){ float v = cw[t*CC + c]; s += v*v; }
        g_c2[t] = s;
    }
}

// ---------------- fused encode: single-stage overlapped ----------------
__global__ __launch_bounds__(TPB_ENC, 1) void k_encode(
    const float* __restrict__ x,
    const float* __restrict__ cw,
    const float* __restrict__ smo)
{
    extern __shared__ char smem[];
    const uint32_t sb = smem_u32(smem);
    const int t = threadIdx.x;
    const int lane = t & 31;
    const int wid  = t >> 5;
    const int g4 = lane >> 2, t4 = lane & 3;

    // ---- cw -> fp16 hi plane (once) ----
    {
        const int row = t >> 4, seg = t & 15;
        const float4* crow = (const float4*)(cw + row*CC) + seg*4;
        float4 v0 = crow[0], v1 = crow[1], v2 = crow[2], v3 = crow[3];
        uint2 h0 = hi2h(v0), h1 = hi2h(v1), h2 = hi2h(v2), h3 = hi2h(v3);
        char* hdst = smem + CWO + row*PCW2 + seg*32;
        ((uint4*)hdst)[0] = make_uint4(h0.x,h0.y,h1.x,h1.y);
        ((uint4*)hdst)[1] = make_uint4(h2.x,h2.y,h3.x,h3.y);
    }

    // B-warp softmax constants
    float c2r[8], smr[8];
    if (wid < 4){
        #pragma unroll
        for (int j = 0; j < 8; j++){
            int k = (j >> 1)*8 + t4*2 + (j & 1);
            c2r[j] = g_c2[k]; smr[j] = smo[k];
        }
    }

    // accumulators
    float accC[16][4];
    #pragma unroll
    for (int i = 0; i < 16; i++)
        #pragma unroll
        for (int j = 0; j < 4; j++) accC[i][j] = 0.f;
    float wsum_acc[8];
    #pragma unroll
    for (int j = 0; j < 8; j++) wsum_acc[j] = 0.f;

    // tile range
    const int t0 = (int)(((long long)blockIdx.x     * TILES_TOTAL) / GRID_ENC);
    const int t1 = (int)(((long long)(blockIdx.x+1) * TILES_TOTAL) / GRID_ENC);

    // GEMM1 (warps 0-3)
    const uint32_t aoff1 = (uint32_t)(wid*16 + (lane & 15)) * PX2 + (uint32_t)((lane >> 4) * 16);
    const uint32_t boff1 = (uint32_t)((lane & 7) + ((lane >> 4) << 3)) * PCW2
                         + (uint32_t)(((lane >> 3) & 1) * 16);
    // GEMM2 (warps 4-15): term s2 in {whi.xhi, whi.xlo, wlo.xhi} x col-quarter q
    const int wc = wid - 4;
    const int s2 = wc >> 2, q = wc & 3;
    const uint32_t a2base = (uint32_t)(lane & 15) * PWT2 + (uint32_t)((lane >> 4) * 16);
    const uint32_t b2base = (uint32_t)(lane & 15) * PX2 + (uint32_t)((lane >> 4) * 16);
    const int ct = t - 128;    // C-thread index [0,384)

    // ---- prologue: all threads LDG+convert slot t of tile t0 ----
    {
        float4 v[8];
        ldg_slot(v, x, t0, t);
        convert_slot(smem, v, t0 & 1, t);
    }
    __syncthreads();

    for (int tt = t0; tt < t1; tt++){
        const int cur = tt & 1, nxt = cur ^ 1;
        const bool haveNext = (tt + 1 < t1);
        const bool boundary = (tt > t0) && ((tt >> 8) != ((tt - 1) >> 8));
        const int bp = (tt - 1) >> 8;

        if (wid < 4){
            // wsum flush (covers tiles <= tt-1)
            if (boundary){
                float red[8];
                #pragma unroll
                for (int j = 0; j < 8; j++){
                    float s = wsum_acc[j];
                    s += __shfl_xor_sync(0xffffffffu, s, 4);
                    s += __shfl_xor_sync(0xffffffffu, s, 8);
                    s += __shfl_xor_sync(0xffffffffu, s, 16);
                    red[j] = s; wsum_acc[j] = 0.f;
                }
                if (g4 == 0){
                    #pragma unroll
                    for (int j = 0; j < 8; j++){
                        int k = (j >> 1)*8 + t4*2 + (j & 1);
                        atomicAdd(&g_wsum[bp*KK + k], red[j]);
                    }
                }
            }
            // GEMM1(tt)
            const uint32_t xhiC = XH0 + (uint32_t)cur*XPAR;
            float d[4][4];
            #pragma unroll
            for (int i = 0; i < 4; i++)
                #pragma unroll
                for (int j = 0; j < 4; j++) d[i][j] = 0.f;
            #pragma unroll 4
            for (int kt = 0; kt < 16; kt++){
                uint32_t a[4], b0[4], b1[4];
                ldsm4(a,  sb + xhiC + aoff1 + kt*32);
                ldsm4(b0, sb + CWO + boff1 + kt*32);
                ldsm4(b1, sb + CWO + boff1 + 16*PCW2 + kt*32);
                mmah(d[0], a, b0[0], b0[1]);
                mmah(d[1], a, b0[2], b0[3]);
                mmah(d[2], a, b1[0], b1[1]);
                mmah(d[3], a, b1[2], b1[3]);
            }
            // softmax from fragments
            const int px0 = wid*16 + g4, px1 = px0 + 8;
            const float* x2p = (const float*)(smem + X2O + cur*256);
            const float xa = x2p[px0], xb = x2p[px1];
            float ea[8], eb[8];
            float mxa = -1e30f, mxb = -1e30f;
            #pragma unroll
            for (int j = 0; j < 8; j++){
                int nt = j >> 1, i = j & 1;
                float la = (xa - 2.f*d[nt][i]     + c2r[j]) * smr[j];
                float lb = (xb - 2.f*d[nt][2 + i] + c2r[j]) * smr[j];
                ea[j] = la; eb[j] = lb;
                mxa = fmaxf(mxa, la); mxb = fmaxf(mxb, lb);
            }
            mxa = fmaxf(mxa, __shfl_xor_sync(0xffffffffu, mxa, 1));
            mxa = fmaxf(mxa, __shfl_xor_sync(0xffffffffu, mxa, 2));
            mxb = fmaxf(mxb, __shfl_xor_sync(0xffffffffu, mxb, 1));
            mxb = fmaxf(mxb, __shfl_xor_sync(0xffffffffu, mxb, 2));
            float sa = 0.f, sbv = 0.f;
            #pragma unroll
            for (int j = 0; j < 8; j++){
                ea[j] = __expf(ea[j] - mxa); sa  += ea[j];
                eb[j] = __expf(eb[j] - mxb); sbv += eb[j];
            }
            sa  += __shfl_xor_sync(0xffffffffu, sa, 1);
            sa  += __shfl_xor_sync(0xffffffffu, sa, 2);
            sbv += __shfl_xor_sync(0xffffffffu, sbv, 1);
            sbv += __shfl_xor_sync(0xffffffffu, sbv, 2);
            const float inva = 1.f / sa, invb = 1.f / sbv;
            char* wh = smem + WT0 + cur*9216;
            char* wl = wh + 4608;
            #pragma unroll
            for (int j = 0; j < 8; j++){
                int k = (j >> 1)*8 + t4*2 + (j & 1);
                float wa = ea[j]*inva, wb = eb[j]*invb;
                wsum_acc[j] += wa + wb;
                __half ha = __float2half_rn(wa);
                __half hb = __float2half_rn(wb);
                *(__half*)(wh + k*PWT2 + px0*2) = ha;
                *(__half*)(wh + k*PWT2 + px1*2) = hb;
                *(__half*)(wl + k*PWT2 + px0*2) = __float2half_rn(wa - __half2float(ha));
                *(__half*)(wl + k*PWT2 + px1*2) = __float2half_rn(wb - __half2float(hb));
            }
        } else {
            // C-warps: early LDG for slot1 of tile tt+1 (hidden under GEMM2)
            float4 v[8];
            if (haveNext) ldg_slot(v, x, tt + 1, ct);

            // GEMM2(tt-1) from wT[nxt], x planes[nxt]
            if (tt > t0){
                const uint32_t apl = WT0 + (uint32_t)nxt*9216 + (s2 == 2 ? 4608u : 0u);
                const uint32_t bpl = XH0 + (uint32_t)nxt*XPAR + (s2 == 1 ? 33792u : 0u);
                #pragma unroll
                for (int pt = 0; pt < 4; pt++){
                    uint32_t af0[4], af1[4];
                    ldsm4(af0, sb + apl + a2base + pt*32);
                    ldsm4(af1, sb + apl + a2base + 16*PWT2 + pt*32);
                    #pragma unroll
                    for (int hf = 0; hf < 4; hf++){
                        uint32_t bf[4];
                        ldsm4t(bf, sb + bpl + b2base + pt*16*PX2 + (uint32_t)(q*64 + hf*16)*2);
                        mmah(accC[hf*2      ], af0, bf[0], bf[1]);
                        mmah(accC[hf*2 + 1  ], af0, bf[2], bf[3]);
                        mmah(accC[8 + hf*2  ], af1, bf[0], bf[1]);
                        mmah(accC[8 + hf*2+1], af1, bf[2], bf[3]);
                    }
                }
                // accC flush AFTER GEMM2(tt-1) (covers tiles <= tt-1)
                if (boundary){
                    #pragma unroll
                    for (int mt = 0; mt < 2; mt++)
                        #pragma unroll
                        for (int hf = 0; hf < 4; hf++)
                            #pragma unroll
                            for (int hv = 0; hv < 2; hv++){
                                int i = mt*8 + hf*2 + hv;
                                float* base = g_agg + ((size_t)bp*KK + mt*16 + g4)*CC
                                            + q*64 + hf*16 + hv*8 + t4*2;
                                atomicAdd(base,            accC[i][0]);
                                atomicAdd(base + 1,        accC[i][1]);
                                atomicAdd(base + 8*CC,     accC[i][2]);
                                atomicAdd(base + 8*CC + 1, accC[i][3]);
                                accC[i][0] = accC[i][1] = accC[i][2] = accC[i][3] = 0.f;
                            }
                }
            }
            // all C-warps done reading x[nxt] before conversion overwrites it
            asm volatile("bar.sync 3, 384;" ::: "memory");
            if (haveNext){
                convert_slot(smem, v, nxt, ct);
                if (ct < 128){
                    float4 v2[8];
                    ldg_slot(v2, x, tt + 1, ct + 384);
                    convert_slot(smem, v2, nxt, ct + 384);
                }
            }
        }
        __syncthreads();
    }

    // ---- epilogue: GEMM2(t1-1) + final flushes ----
    const int bl2 = (t1 - 1) >> 8;
    if (wid >= 4){
        const int lp = (t1 - 1) & 1;
        const uint32_t apl = WT0 + (uint32_t)lp*9216 + (s2 == 2 ? 4608u : 0u);
        const uint32_t bpl = XH0 + (uint32_t)lp*XPAR + (s2 == 1 ? 33792u : 0u);
        #pragma unroll
        for (int pt = 0; pt < 4; pt++){
            uint32_t af0[4], af1[4];
            ldsm4(af0, sb + apl + a2base + pt*32);
            ldsm4(af1, sb + apl + a2base + 16*PWT2 + pt*32);
            #pragma unroll
            for (int hf = 0; hf < 4; hf++){
                uint32_t bf[4];
                ldsm4t(bf, sb + bpl + b2base + pt*16*PX2 + (uint32_t)(q*64 + hf*16)*2);
                mmah(accC[hf*2      ], af0, bf[0], bf[1]);
                mmah(accC[hf*2 + 1  ], af0, bf[2], bf[3]);
                mmah(accC[8 + hf*2  ], af1, bf[0], bf[1]);
                mmah(accC[8 + hf*2+1], af1, bf[2], bf[3]);
            }
        }
        #pragma unroll
        for (int mt = 0; mt < 2; mt++)
            #pragma unroll
            for (int hf = 0; hf < 4; hf++)
                #pragma unroll
                for (int hv = 0; hv < 2; hv++){
                    int i = mt*8 + hf*2 + hv;
                    float* base = g_agg + ((size_t)bl2*KK + mt*16 + g4)*CC
                                + q*64 + hf*16 + hv*8 + t4*2;
                    atomicAdd(base,            accC[i][0]);
                    atomicAdd(base + 1,        accC[i][1]);
                    atomicAdd(base + 8*CC,     accC[i][2]);
                    atomicAdd(base + 8*CC + 1, accC[i][3]);
                }
    } else {
        float red[8];
        #pragma unroll
        for (int j = 0; j < 8; j++){
            float s = wsum_acc[j];
            s += __shfl_xor_sync(0xffffffffu, s, 4);
            s += __shfl_xor_sync(0xffffffffu, s, 8);
            s += __shfl_xor_sync(0xffffffffu, s, 16);
            red[j] = s;
        }
        if (g4 == 0){
            #pragma unroll
            for (int j = 0; j < 8; j++){
                int k = (j >> 1)*8 + t4*2 + (j & 1);
                atomicAdd(&g_wsum[bl2*KK + k], red[j]);
            }
        }
    }
}

// ---------------- heads ----------------
__global__ void k_heads(
    const float* __restrict__ cw,
    const float* __restrict__ gamma, const float* __restrict__ beta,
    const float* __restrict__ mean,  const float* __restrict__ var,
    const float* __restrict__ Wenc,  const float* __restrict__ benc,
    const float* __restrict__ Wse,   const float* __restrict__ bse,
    float* __restrict__ out)
{
    const int b = blockIdx.x;
    const int c = threadIdx.x;
    __shared__ float enc[CC];

    float acc = 0.f;
    #pragma unroll
    for (int k = 0; k < KK; k++){
        float a  = g_agg[(b*KK + k)*CC + c] - g_wsum[b*KK + k] * cw[k*CC + c];
        float bn = (a - mean[k]) * rsqrtf(var[k] + BN_EPS) * gamma[k] + beta[k];
        acc += fmaxf(bn, 0.f);
    }
    enc[c] = acc;
    __syncthreads();

    float s = benc[c];
    #pragma unroll 8
    for (int i = 0; i < CC; i++) s += enc[i] * Wenc[i*CC + c];
    g_attn[b*CC + c] = 1.f / (1.f + __expf(-s));

    if (c < NCLS){
        float s2 = bse[c];
        #pragma unroll 8
        for (int i = 0; i < CC; i++) s2 += enc[i] * Wse[i*NCLS + c];
        out[(size_t)BB*NPIX*CC + b*NCLS + c] = 1.f / (1.f + __expf(-s2));
    }
}

// ---------------- rescale ----------------
__global__ void k_scale(const float* __restrict__ x, float* __restrict__ out){
    const int F4 = NPIX*CC/4;
    int idx = blockIdx.x*blockDim.x + threadIdx.x;
    int b  = idx / F4;
    int r  = idx - b*F4;
    int c4 = r & 63;
    float4 a = ((const float4*)g_attn)[b*64 + c4];
    float4 v = __ldcs((const float4*)x + idx);
    v.x *= a.x; v.y *= a.y; v.z *= a.z; v.w *= a.w;
    __stcs((float4*)out + idx, v);
}

extern "C" void kernel_launch(void* const* d_in, const int* in_sizes, int n_in,
                              void* d_out, int out_size)
{
    const float* x     = (const float*)d_in[0];
    const float* cw    = (const float*)d_in[1];
    const float* smo   = (const float*)d_in[2];
    const float* gamma = (const float*)d_in[3];
    const float* beta  = (const float*)d_in[4];
    const float* mean  = (const float*)d_in[5];
    const float* var   = (const float*)d_in[6];
    const float* Wenc  = (const float*)d_in[7];
    const float* benc  = (const float*)d_in[8];
    const float* Wse   = (const float*)d_in[9];
    const float* bse   = (const float*)d_in[10];
    float* out = (float*)d_out;

    cudaFuncSetAttribute(k_encode, cudaFuncAttributeMaxDynamicSharedMemorySize, SMEM_ENC);

    int init_total = BB*KK*CC + BB*KK;
    k_init<<<(init_total + 255)/256, 256>>>(cw);
    k_encode<<<GRID_ENC, TPB_ENC, SMEM_ENC>>>(x, cw, smo);
    k_heads<<<BB, CC>>>(cw, gamma, beta, mean, var, Wenc, benc, Wse, bse, out);
    k_scale<<<(BB*NPIX*CC/4)/256, 256>>>(x, out);
}